// round 12
// baseline (speedup 1.0000x reference)
#include <cuda_runtime.h>
#include <math.h>

#define Bn   4096
#define Cn   2000
#define CPB  16           // classes per block (125*16 == 2000)
#define T1   1024
#define NB1  125
#define GRP  64           // groups in scan phase (T1 / CPB)
#define SEGW 9            // slot stride per thread segment (8 slots + pad)
#define CSTR 2305         // class stride in s_pbuf (256*9 + 1 pad)

#define L2E 1.4426950408889634f
#define LN2 0.6931471805599453f

__device__ float g_bceB[NB1];
__device__ int   g_cnt[Cn];
__device__ float g_pdp[NB1];
__device__ float g_pdn[NB1];
__device__ int   g_arrive = 0;
__device__ int   g_tick   = 0;

__device__ __forceinline__ float ex2f_(float x){ float r; asm("ex2.approx.ftz.f32 %0,%1;":"=f"(r):"f"(x)); return r; }
__device__ __forceinline__ float lg2f_(float x){ float r; asm("lg2.approx.ftz.f32 %0,%1;":"=f"(r):"f"(x)); return r; }
__device__ __forceinline__ float rcpf_(float x){ float r; asm("rcp.approx.ftz.f32 %0,%1;":"=f"(r):"f"(x)); return r; }
__device__ __forceinline__ float sigm_(float x){ return rcpf_(1.0f + ex2f_(x * -L2E)); }

// merge other sorted triple (v0<=v1<=v2) into mine (m0<=m1<=m2)
#define MERGE3(m0,m1,m2,v0,v1,v2)                                   \
{                                                                    \
    float h0 = fmaxf(m0, v0); m0 = fminf(m0, v0);                    \
    float h1 = fmaxf(m1, h0); m1 = fminf(m1, h0);                    \
    m2 = fminf(m2, h1);                                              \
    float g1 = fmaxf(m1, v1); m1 = fminf(m1, v1);                    \
    m2 = fminf(m2, g1);                                              \
    m2 = fminf(m2, v2);                                              \
}

#define N_BUF   (CPB*CSTR)       // 36880 floats (>= Cn ints for count staging reuse)
#define N_W3    (3*512)
#define N_W4    (4*GRP*CPB)
#define SM_FLOATS (N_BUF + N_W3 + N_W4 + 2*T1)
#define SM_BYTES  (SM_FLOATS * 4)   // 186,432 B dynamic

__global__ __launch_bounds__(T1, 1) void k1(const float* __restrict__ inp,
                                            const float* __restrict__ tgt,
                                            float* __restrict__ out)
{
    extern __shared__ float sm[];
    float* s_pbuf = sm;               // [CPB][256 segs][SEGW] positive raw-x ; later: count staging
    float* s_w3   = s_pbuf + N_BUF;   // [3][32*16]  per-warp neg bottom-3 (x-domain)
    float* s_w4   = s_w3 + N_W3;      // [4][GRP*CPB] pos bottom-4 (p-domain) merge
    float* s_red  = s_w4 + N_W4;      // [T1] dneg
    float* s_sp   = s_red + T1;       // [T1] spos

    __shared__ int   s_tc[CPB * 257];   // per-(class, thread-seg) positive counts
    __shared__ int   s_ccnt[CPB];
    __shared__ float f_q[CPB][3];
    __shared__ int   f_cnt[CPB];
    __shared__ float s_dpl[CPB], s_dnl[CPB];
    __shared__ int   s_flag[CPB];
    __shared__ int   s_last;
    __shared__ float s_fr[3][4];
    __shared__ float s_wb[32];

    const int tid  = threadIdx.x;
    const int lane = tid & 31;
    const int wrp  = tid >> 5;
    const int bIdx = blockIdx.x;

    // ---------------- main streaming pass: two row streams, private segments ----------------
    const int q  = tid & 3;           // class quad (local classes 4q..4q+3)
    const int gg = tid >> 2;          // rowgroup / segment index 0..255
    const int c0 = bIdx * CPB + 4 * q;

    float* sbase = s_pbuf + (4 * q) * CSTR + gg * SEGW;

    float nv00 = INFINITY, nv01 = INFINITY, nv02 = INFINITY;
    float nv10 = INFINITY, nv11 = INFINITY, nv12 = INFINITY;
    float nv20 = INFINITY, nv21 = INFINITY, nv22 = INFINITY;
    float nv30 = INFINITY, nv31 = INFINITY, nv32 = INFINITY;
    float bsum = 0.0f;   // sum of lg2(prod) terms (log2 units)
    float bpos = 0.0f;   // sum of max(x, 0) (natural units)
    float xt   = 0.0f;   // sum of x * t
    int cnt0 = 0, cnt1 = 0, cnt2 = 0, cnt3 = 0;

    const float4* pa = (const float4*)(inp + (size_t)gg * Cn + c0);
    const float4* ta = (const float4*)(tgt + (size_t)gg * Cn + c0);
    const float4* pb = (const float4*)(inp + (size_t)(gg + 2048) * Cn + c0);
    const float4* tb = (const float4*)(tgt + (size_t)(gg + 2048) * Cn + c0);
    const int st4 = (256 * Cn) / 4;

    #pragma unroll 1
    for (int it = 0; it < 8; ++it) {
        float4 xA = __ldg(pa);
        float4 tA = __ldg(ta);
        float4 xB = __ldg(pb);
        float4 tB = __ldg(tb);
        pa += st4; ta += st4; pb += st4; tb += st4;

        float prod = 1.0f;   // prod of (1 + e^{-|x|}) over this iteration's 8 elems, <= 256

        #define ELEM(X, T, KIDX, N0, N1, N2, CNT)                             \
        {                                                                     \
            float x = (X), t = (T);                                           \
            float e = ex2f_(fabsf(x) * -L2E);                                 \
            bpos += fmaxf(x, 0.0f);                                           \
            prod *= (1.0f + e);                                               \
            xt = fmaf(x, t, xt);                                              \
            float nk = fmaf(t, 1e30f, x);                                     \
            float e0 = fmaxf(N0, nk); N0 = fminf(N0, nk);                     \
            float e1 = fmaxf(N1, e0); N1 = fminf(N1, e0);                     \
            N2 = fminf(N2, e1);                                               \
            if (t == 1.0f) {                                                  \
                sbase[(KIDX) * CSTR + min(CNT, 7)] = x;                       \
                CNT++;                                                        \
            }                                                                 \
        }
        ELEM(xA.x, tA.x, 0, nv00, nv01, nv02, cnt0)
        ELEM(xA.y, tA.y, 1, nv10, nv11, nv12, cnt1)
        ELEM(xA.z, tA.z, 2, nv20, nv21, nv22, cnt2)
        ELEM(xA.w, tA.w, 3, nv30, nv31, nv32, cnt3)
        ELEM(xB.x, tB.x, 0, nv00, nv01, nv02, cnt0)
        ELEM(xB.y, tB.y, 1, nv10, nv11, nv12, cnt1)
        ELEM(xB.z, tB.z, 2, nv20, nv21, nv22, cnt2)
        ELEM(xB.w, tB.w, 3, nv30, nv31, nv32, cnt3)
        #undef ELEM

        bsum += lg2f_(prod);
    }

    // ---- stash per-(class, segment) counts ----
    s_tc[(4*q + 0) * 257 + gg] = cnt0;
    s_tc[(4*q + 1) * 257 + gg] = cnt1;
    s_tc[(4*q + 2) * 257 + gg] = cnt2;
    s_tc[(4*q + 3) * 257 + gg] = cnt3;

    // ---- butterfly merge neg bottom-3 across the 8 lanes sharing each class ----
    #pragma unroll
    for (int off = 4; off <= 16; off <<= 1) {
        float v0, v1, v2;
        v0 = __shfl_xor_sync(0xffffffffu, nv00, off);
        v1 = __shfl_xor_sync(0xffffffffu, nv01, off);
        v2 = __shfl_xor_sync(0xffffffffu, nv02, off);
        MERGE3(nv00, nv01, nv02, v0, v1, v2)
        v0 = __shfl_xor_sync(0xffffffffu, nv10, off);
        v1 = __shfl_xor_sync(0xffffffffu, nv11, off);
        v2 = __shfl_xor_sync(0xffffffffu, nv12, off);
        MERGE3(nv10, nv11, nv12, v0, v1, v2)
        v0 = __shfl_xor_sync(0xffffffffu, nv20, off);
        v1 = __shfl_xor_sync(0xffffffffu, nv21, off);
        v2 = __shfl_xor_sync(0xffffffffu, nv22, off);
        MERGE3(nv20, nv21, nv22, v0, v1, v2)
        v0 = __shfl_xor_sync(0xffffffffu, nv30, off);
        v1 = __shfl_xor_sync(0xffffffffu, nv31, off);
        v2 = __shfl_xor_sync(0xffffffffu, nv32, off);
        MERGE3(nv30, nv31, nv32, v0, v1, v2)
    }
    if (lane < 4) {   // lane == q for lanes 0..3
        const int b = wrp * CPB;
        s_w3[0*512 + b + 4*lane + 0] = nv00; s_w3[1*512 + b + 4*lane + 0] = nv01; s_w3[2*512 + b + 4*lane + 0] = nv02;
        s_w3[0*512 + b + 4*lane + 1] = nv10; s_w3[1*512 + b + 4*lane + 1] = nv11; s_w3[2*512 + b + 4*lane + 1] = nv12;
        s_w3[0*512 + b + 4*lane + 2] = nv20; s_w3[1*512 + b + 4*lane + 2] = nv21; s_w3[2*512 + b + 4*lane + 2] = nv22;
        s_w3[0*512 + b + 4*lane + 3] = nv30; s_w3[1*512 + b + 4*lane + 3] = nv31; s_w3[2*512 + b + 4*lane + 3] = nv32;
    }

    // bce: per-thread combine then per-warp reduce
    // bce = ln2 * bsum + bpos - xt
    float bce = fmaf(bsum, LN2, bpos - xt);
    #pragma unroll
    for (int o = 16; o > 0; o >>= 1) bce += __shfl_xor_sync(0xffffffffu, bce, o);
    if (lane == 0) s_wb[wrp] = bce;
    __syncthreads();

    // ---- per-class count totals (warp per class) + publish + bce publish ----
    if (wrp < CPB) {
        int v = 0;
        const int* tb2 = s_tc + wrp * 257 + lane * 8;
        #pragma unroll
        for (int i = 0; i < 8; i++) v += tb2[i];
        #pragma unroll
        for (int o = 16; o > 0; o >>= 1) v += __shfl_xor_sync(0xffffffffu, v, o);
        if (lane == 0) {
            s_ccnt[wrp] = v;
            g_cnt[bIdx * CPB + wrp] = v;
            __threadfence();
        }
    }
    if (tid == T1 - 1) {
        float b = 0.0f;
        #pragma unroll
        for (int w = 0; w < 32; w++) b += s_wb[w];
        g_bceB[bIdx] = b;
        __threadfence();
    }
    __syncthreads();
    if (tid == 0) atomicAdd(&g_arrive, 1);

    // ---- merge neg bottom-3: 32 warp entries -> 1, per class ----
    const int cl = tid & (CPB - 1);
    const int g  = tid >> 4;
    float m0, m1, m2;
    if (g < 32) {
        m0 = s_w3[0*512 + g*CPB + cl];
        m1 = s_w3[1*512 + g*CPB + cl];
        m2 = s_w3[2*512 + g*CPB + cl];
    }
    for (int s = 16; s > 0; s >>= 1) {
        __syncthreads();
        if (g < s) {
            float v0 = s_w3[0*512 + (g+s)*CPB + cl];
            float v1 = s_w3[1*512 + (g+s)*CPB + cl];
            float v2 = s_w3[2*512 + (g+s)*CPB + cl];
            MERGE3(m0, m1, m2, v0, v1, v2)
            s_w3[0*512 + g*CPB + cl] = m0;
            s_w3[1*512 + g*CPB + cl] = m1;
            s_w3[2*512 + g*CPB + cl] = m2;
        }
    }
    __syncthreads();

    if (tid < CPB) {
        f_q[tid][0] = sigm_(s_w3[0*512 + tid]);
        f_q[tid][1] = sigm_(s_w3[1*512 + tid]);
        f_q[tid][2] = sigm_(s_w3[2*512 + tid]);
        f_cnt[tid]  = s_ccnt[tid];
    }
    __syncthreads();

    // ---- scan private segments: sigmoid, bottom-4 p, spos, dneg ----
    const int   cnt = f_cnt[cl];
    const int   nn  = min(3, Bn - cnt);
    const float q0 = f_q[cl][0], q1 = f_q[cl][1], q2 = f_q[cl][2];
    const float w0 = (0 < nn) ? 1.0f : 0.0f;
    const float w1 = (1 < nn) ? 1.0f : 0.0f;
    const float w2 = (2 < nn) ? 1.0f : 0.0f;

    float a0 = INFINITY, a1 = INFINITY, a2 = INFINITY, a3 = INFINITY;
    float spos = 0.0f, sdn = 0.0f;
    {
        const float* cbase = s_pbuf + cl * CSTR;
        const int*   tbase = s_tc + cl * 257;
        #pragma unroll
        for (int t4 = 0; t4 < 4; t4++) {
            const int tseg  = g * 4 + t4;
            const int bound = min(tbase[tseg], 8);
            const float* sp = cbase + tseg * SEGW;
            for (int k = 0; k < bound; k++) {
                float xr = sp[k];
                float p  = sigm_(xr);
                spos += p;
                sdn += w0 * fabsf(p - q0) + w1 * fabsf(p - q1) + w2 * fabsf(p - q2);
                float h0 = fmaxf(a0, p); a0 = fminf(a0, p);
                float h1 = fmaxf(a1, h0); a1 = fminf(a1, h0);
                float h2 = fmaxf(a2, h1); a2 = fminf(a2, h1);
                a3 = fminf(a3, h2);
            }
        }
    }
    const int base = g * CPB + cl;
    s_w4[base] = a0; s_w4[1024 + base] = a1;
    s_w4[2048 + base] = a2; s_w4[3072 + base] = a3;
    s_red[base] = sdn; s_sp[base] = spos;

    for (int s = GRP >> 1; s > 0; s >>= 1) {
        __syncthreads();
        if (g < s) {
            const int b = (g + s) * CPB + cl;
            #pragma unroll
            for (int j = 0; j < 4; j++) {
                float v = s_w4[j * 1024 + b];
                float h0 = fmaxf(a0, v); a0 = fminf(a0, v);
                float h1 = fmaxf(a1, h0); a1 = fminf(a1, h0);
                float h2 = fmaxf(a2, h1); a2 = fminf(a2, h1);
                a3 = fminf(a3, h2);
            }
            s_w4[base] = a0; s_w4[1024 + base] = a1;
            s_w4[2048 + base] = a2; s_w4[3072 + base] = a3;
            s_red[base] += s_red[b];
            s_sp[base]  += s_sp[b];
        }
    }
    __syncthreads();

    // ---- per-class finalize: analytic dpos + scaled dneg (into smem) ----
    if (tid < CPB) {
        const int c2  = tid;
        const int npc = f_cnt[c2];
        const int t4  = min(4, npc);
        const int m   = min(3, max(npc - 1, 0));
        const int nn2 = min(3, Bn - npc);
        float tv[4] = { s_w4[c2], s_w4[1024 + c2], s_w4[2048 + c2], s_w4[3072 + c2] };
        float Tm = 0.0f;
        #pragma unroll
        for (int j = 0; j < 3; j++) if (j < m) Tm += tv[j];
        float Sh = 0.0f;
        #pragma unroll
        for (int r = 0; r < 4; r++) if (r < t4) Sh += tv[r];
        float tail = (float)m * (s_sp[c2] - Sh) - (float)(npc - t4) * Tm;
        float head = 0.0f;
        #pragma unroll
        for (int r = 0; r < 4; r++) {
            if (r < t4) {
                #pragma unroll
                for (int j = 0; j < 4; j++) {
                    if (j != r) {
                        int pa2 = j - (j > r ? 1 : 0);
                        if (pa2 < m) head += fabsf(tv[r] - tv[j]);
                    }
                }
            }
        }
        s_dpl[c2] = (float)nn2 * (tail + head);
        s_dnl[c2] = (float)m * s_red[c2];
    }

    // ---- wait for all blocks' counts ----
    if (tid == 0) {
        volatile int* va = &g_arrive;
        while (*va < NB1) { }
    }
    __syncthreads();
    __threadfence();

    // ---- stage all 2000 counts into (now free) s_pbuf ----
    int* sci = (int*)s_pbuf;
    {
        const volatile int* vc = (const volatile int*)g_cnt;
        for (int i = tid; i < Cn; i += T1) sci[i] = vc[i];
    }
    __syncthreads();

    // ---- minority test for this block's 16 classes (16 warps) ----
    if (wrp < CPB) {
        const int cg = bIdx * CPB + wrp;
        const int v  = sci[cg];
        int S = 0;
        for (int c2 = lane; c2 < Cn; c2 += 32) {
            int v2 = sci[c2];
            bool le = (v2 < v) || (v2 == v && c2 <= cg);
            S += le ? v2 : 0;
        }
        #pragma unroll
        for (int o = 16; o > 0; o >>= 1) S += __shfl_xor_sync(0xffffffffu, S, o);
        if (lane == 0) s_flag[wrp] = ((S <= Bn / 2) && (v >= 2)) ? 1 : 0;
    }
    __syncthreads();

    // ---- per-block masked partials + ticket ----
    if (tid == 0) {
        float pdp = 0.0f, pdn = 0.0f;
        #pragma unroll
        for (int i = 0; i < CPB; i++) {
            if (s_flag[i]) { pdp += s_dpl[i]; pdn += s_dnl[i]; }
        }
        g_pdp[bIdx] = pdp;
        g_pdn[bIdx] = pdn;
        __threadfence();
        int tck = atomicAdd(&g_tick, 1);
        s_last = (tck == NB1 - 1) ? 1 : 0;
    }
    __syncthreads();

    // ---- last block: final combine ----
    if (s_last) {
        __threadfence();
        float dp = 0.0f, dn = 0.0f, bc = 0.0f;
        if (tid < NB1) {
            dp = ((const volatile float*)g_pdp)[tid];
            dn = ((const volatile float*)g_pdn)[tid];
            bc = ((const volatile float*)g_bceB)[tid];
        }
        #pragma unroll
        for (int o = 16; o > 0; o >>= 1) {
            dp += __shfl_xor_sync(0xffffffffu, dp, o);
            dn += __shfl_xor_sync(0xffffffffu, dn, o);
            bc += __shfl_xor_sync(0xffffffffu, bc, o);
        }
        if (lane == 0 && wrp < 4) { s_fr[0][wrp] = dp; s_fr[1][wrp] = dn; s_fr[2][wrp] = bc; }
        __syncthreads();
        if (tid == 0) {
            float fdp = s_fr[0][0] + s_fr[0][1] + s_fr[0][2] + s_fr[0][3];
            float fdn = s_fr[1][0] + s_fr[1][1] + s_fr[1][2] + s_fr[1][3];
            float fbc = s_fr[2][0] + s_fr[2][1] + s_fr[2][2] + s_fr[2][3];
            float crl = fmaxf(fdp - fdn + 1.0f, 0.0f);        // MARGIN = 1
            float bce_mean = fbc / (float)(Bn * Cn);
            out[0] = 0.001f * crl + 0.999f * bce_mean;        // ALPHA = 0.001
            g_arrive = 0;                                      // reset for graph replay
            g_tick   = 0;
        }
    }
}

extern "C" void kernel_launch(void* const* d_in, const int* in_sizes, int n_in,
                              void* d_out, int out_size)
{
    (void)in_sizes; (void)n_in; (void)out_size;
    const float* inp = (const float*)d_in[0];
    const float* tgt = (const float*)d_in[1];
    cudaFuncSetAttribute(k1, cudaFuncAttributeMaxDynamicSharedMemorySize, SM_BYTES);
    k1<<<NB1, T1, SM_BYTES>>>(inp, tgt, (float*)d_out);
}

// round 13
// speedup vs baseline: 1.0102x; 1.0102x over previous
#include <cuda_runtime.h>
#include <math.h>

#define Bn   4096
#define Cn   2000
#define CPB  16           // classes per block (125*16 == 2000)
#define T1   1024
#define NB1  125
#define GRP  64           // groups in scan phase (T1 / CPB)
#define SEGW 9            // slot stride per thread segment (8 slots + pad)
#define CSTR 2305         // class stride in s_pbuf (256*9 + 1 pad)
#define OFF1 ((1024 * Cn) / 4)   // +1024 rows in float4 units (8,192,000 B imm — fits 24-bit)

#define L2E 1.4426950408889634f
#define LN2 0.6931471805599453f

__device__ float g_bceB[NB1];
__device__ int   g_cnt[Cn];
__device__ float g_pdp[NB1];
__device__ float g_pdn[NB1];
__device__ int   g_arrive = 0;
__device__ int   g_tick   = 0;

__device__ __forceinline__ float ex2f_(float x){ float r; asm("ex2.approx.ftz.f32 %0,%1;":"=f"(r):"f"(x)); return r; }
__device__ __forceinline__ float lg2f_(float x){ float r; asm("lg2.approx.ftz.f32 %0,%1;":"=f"(r):"f"(x)); return r; }
__device__ __forceinline__ float rcpf_(float x){ float r; asm("rcp.approx.ftz.f32 %0,%1;":"=f"(r):"f"(x)); return r; }
__device__ __forceinline__ float sigm_(float x){ return rcpf_(1.0f + ex2f_(x * -L2E)); }

// merge other sorted triple (v0<=v1<=v2) into mine (m0<=m1<=m2)
#define MERGE3(m0,m1,m2,v0,v1,v2)                                   \
{                                                                    \
    float h0 = fmaxf(m0, v0); m0 = fminf(m0, v0);                    \
    float h1 = fmaxf(m1, h0); m1 = fminf(m1, h0);                    \
    m2 = fminf(m2, h1);                                              \
    float g1 = fmaxf(m1, v1); m1 = fminf(m1, v1);                    \
    m2 = fminf(m2, g1);                                              \
    m2 = fminf(m2, v2);                                              \
}

#define N_BUF   (CPB*CSTR)       // 36880 floats (>= Cn ints for count staging reuse)
#define N_W3    (3*512)
#define N_W4    (4*GRP*CPB)
#define SM_FLOATS (N_BUF + N_W3 + N_W4 + 2*T1)
#define SM_BYTES  (SM_FLOATS * 4)   // 186,432 B dynamic

__global__ __launch_bounds__(T1, 1) void k1(const float* __restrict__ inp,
                                            const float* __restrict__ tgt,
                                            float* __restrict__ out)
{
    extern __shared__ float sm[];
    float* s_pbuf = sm;               // [CPB][256 segs][SEGW] positive raw-x ; later: count staging
    float* s_w3   = s_pbuf + N_BUF;   // [3][32*16]  per-warp neg bottom-3 (x-domain)
    float* s_w4   = s_w3 + N_W3;      // [4][GRP*CPB] pos bottom-4 (p-domain) merge
    float* s_red  = s_w4 + N_W4;      // [T1] dneg
    float* s_sp   = s_red + T1;       // [T1] spos

    __shared__ int   s_tc[CPB * 257];   // per-(class, thread-seg) positive counts
    __shared__ int   s_ccnt[CPB];
    __shared__ float f_q[CPB][3];
    __shared__ int   f_cnt[CPB];
    __shared__ float s_dpl[CPB], s_dnl[CPB];
    __shared__ int   s_flag[CPB];
    __shared__ int   s_last;
    __shared__ float s_fr[3][4];
    __shared__ float s_wb[32];

    const int tid  = threadIdx.x;
    const int lane = tid & 31;
    const int wrp  = tid >> 5;
    const int bIdx = blockIdx.x;

    // ---------------- main streaming pass: FOUR row streams, private segments ----------------
    const int q  = tid & 3;           // class quad (local classes 4q..4q+3)
    const int gg = tid >> 2;          // rowgroup / segment index 0..255
    const int c0 = bIdx * CPB + 4 * q;

    float* sbase = s_pbuf + (4 * q) * CSTR + gg * SEGW;

    float nv00 = INFINITY, nv01 = INFINITY, nv02 = INFINITY;
    float nv10 = INFINITY, nv11 = INFINITY, nv12 = INFINITY;
    float nv20 = INFINITY, nv21 = INFINITY, nv22 = INFINITY;
    float nv30 = INFINITY, nv31 = INFINITY, nv32 = INFINITY;
    float bsum = 0.0f;   // sum of lg2(prod) terms (log2 units)
    float bpos = 0.0f;   // sum of max(x, 0) (natural units)
    float xt   = 0.0f;   // sum of x * t
    int cnt0 = 0, cnt1 = 0, cnt2 = 0, cnt3 = 0;

    const float4* pa = (const float4*)(inp + (size_t)gg * Cn + c0);          // rows gg, gg+1024 (imm)
    const float4* ta = (const float4*)(tgt + (size_t)gg * Cn + c0);
    const float4* pb = (const float4*)(inp + (size_t)(gg + 2048) * Cn + c0); // rows gg+2048, gg+3072 (imm)
    const float4* tb = (const float4*)(tgt + (size_t)(gg + 2048) * Cn + c0);
    const int st4 = (256 * Cn) / 4;

    #pragma unroll 1
    for (int it = 0; it < 4; ++it) {
        float4 x0 = __ldg(pa);
        float4 x1 = __ldg(pa + OFF1);
        float4 x2 = __ldg(pb);
        float4 x3 = __ldg(pb + OFF1);
        float4 t0 = __ldg(ta);
        float4 t1 = __ldg(ta + OFF1);
        float4 t2 = __ldg(tb);
        float4 t3 = __ldg(tb + OFF1);
        pa += st4; ta += st4; pb += st4; tb += st4;

        float prodA = 1.0f;   // prod of (1 + e^{-|x|}) over 8 elems, <= 256
        float prodB = 1.0f;

        #define ELEM(X, T, KIDX, N0, N1, N2, PROD, CNT)                       \
        {                                                                     \
            float x = (X), t = (T);                                           \
            float e = ex2f_(fabsf(x) * -L2E);                                 \
            bpos += fmaxf(x, 0.0f);                                           \
            PROD *= (1.0f + e);                                               \
            xt = fmaf(x, t, xt);                                              \
            float nk = fmaf(t, 1e30f, x);                                     \
            float e0 = fmaxf(N0, nk); N0 = fminf(N0, nk);                     \
            float e1 = fmaxf(N1, e0); N1 = fminf(N1, e0);                     \
            N2 = fminf(N2, e1);                                               \
            if (t == 1.0f) {                                                  \
                sbase[(KIDX) * CSTR + min(CNT, 7)] = x;                       \
                CNT++;                                                        \
            }                                                                 \
        }
        ELEM(x0.x, t0.x, 0, nv00, nv01, nv02, prodA, cnt0)
        ELEM(x0.y, t0.y, 1, nv10, nv11, nv12, prodA, cnt1)
        ELEM(x0.z, t0.z, 2, nv20, nv21, nv22, prodA, cnt2)
        ELEM(x0.w, t0.w, 3, nv30, nv31, nv32, prodA, cnt3)
        ELEM(x1.x, t1.x, 0, nv00, nv01, nv02, prodA, cnt0)
        ELEM(x1.y, t1.y, 1, nv10, nv11, nv12, prodA, cnt1)
        ELEM(x1.z, t1.z, 2, nv20, nv21, nv22, prodA, cnt2)
        ELEM(x1.w, t1.w, 3, nv30, nv31, nv32, prodA, cnt3)
        ELEM(x2.x, t2.x, 0, nv00, nv01, nv02, prodB, cnt0)
        ELEM(x2.y, t2.y, 1, nv10, nv11, nv12, prodB, cnt1)
        ELEM(x2.z, t2.z, 2, nv20, nv21, nv22, prodB, cnt2)
        ELEM(x2.w, t2.w, 3, nv30, nv31, nv32, prodB, cnt3)
        ELEM(x3.x, t3.x, 0, nv00, nv01, nv02, prodB, cnt0)
        ELEM(x3.y, t3.y, 1, nv10, nv11, nv12, prodB, cnt1)
        ELEM(x3.z, t3.z, 2, nv20, nv21, nv22, prodB, cnt2)
        ELEM(x3.w, t3.w, 3, nv30, nv31, nv32, prodB, cnt3)
        #undef ELEM

        bsum += lg2f_(prodA * prodB);
    }

    // ---- stash per-(class, segment) counts ----
    s_tc[(4*q + 0) * 257 + gg] = cnt0;
    s_tc[(4*q + 1) * 257 + gg] = cnt1;
    s_tc[(4*q + 2) * 257 + gg] = cnt2;
    s_tc[(4*q + 3) * 257 + gg] = cnt3;

    // ---- butterfly merge neg bottom-3 across the 8 lanes sharing each class ----
    #pragma unroll
    for (int off = 4; off <= 16; off <<= 1) {
        float v0, v1, v2;
        v0 = __shfl_xor_sync(0xffffffffu, nv00, off);
        v1 = __shfl_xor_sync(0xffffffffu, nv01, off);
        v2 = __shfl_xor_sync(0xffffffffu, nv02, off);
        MERGE3(nv00, nv01, nv02, v0, v1, v2)
        v0 = __shfl_xor_sync(0xffffffffu, nv10, off);
        v1 = __shfl_xor_sync(0xffffffffu, nv11, off);
        v2 = __shfl_xor_sync(0xffffffffu, nv12, off);
        MERGE3(nv10, nv11, nv12, v0, v1, v2)
        v0 = __shfl_xor_sync(0xffffffffu, nv20, off);
        v1 = __shfl_xor_sync(0xffffffffu, nv21, off);
        v2 = __shfl_xor_sync(0xffffffffu, nv22, off);
        MERGE3(nv20, nv21, nv22, v0, v1, v2)
        v0 = __shfl_xor_sync(0xffffffffu, nv30, off);
        v1 = __shfl_xor_sync(0xffffffffu, nv31, off);
        v2 = __shfl_xor_sync(0xffffffffu, nv32, off);
        MERGE3(nv30, nv31, nv32, v0, v1, v2)
    }
    if (lane < 4) {   // lane == q for lanes 0..3
        const int b = wrp * CPB;
        s_w3[0*512 + b + 4*lane + 0] = nv00; s_w3[1*512 + b + 4*lane + 0] = nv01; s_w3[2*512 + b + 4*lane + 0] = nv02;
        s_w3[0*512 + b + 4*lane + 1] = nv10; s_w3[1*512 + b + 4*lane + 1] = nv11; s_w3[2*512 + b + 4*lane + 1] = nv12;
        s_w3[0*512 + b + 4*lane + 2] = nv20; s_w3[1*512 + b + 4*lane + 2] = nv21; s_w3[2*512 + b + 4*lane + 2] = nv22;
        s_w3[0*512 + b + 4*lane + 3] = nv30; s_w3[1*512 + b + 4*lane + 3] = nv31; s_w3[2*512 + b + 4*lane + 3] = nv32;
    }

    // bce: per-thread combine then per-warp reduce
    // bce = ln2 * bsum + bpos - xt
    float bce = fmaf(bsum, LN2, bpos - xt);
    #pragma unroll
    for (int o = 16; o > 0; o >>= 1) bce += __shfl_xor_sync(0xffffffffu, bce, o);
    if (lane == 0) s_wb[wrp] = bce;
    __syncthreads();

    // ---- per-class count totals (warp per class) + publish + bce publish ----
    if (wrp < CPB) {
        int v = 0;
        const int* tb2 = s_tc + wrp * 257 + lane * 8;
        #pragma unroll
        for (int i = 0; i < 8; i++) v += tb2[i];
        #pragma unroll
        for (int o = 16; o > 0; o >>= 1) v += __shfl_xor_sync(0xffffffffu, v, o);
        if (lane == 0) {
            s_ccnt[wrp] = v;
            g_cnt[bIdx * CPB + wrp] = v;
            __threadfence();
        }
    }
    if (tid == T1 - 1) {
        float b = 0.0f;
        #pragma unroll
        for (int w = 0; w < 32; w++) b += s_wb[w];
        g_bceB[bIdx] = b;
        __threadfence();
    }
    __syncthreads();
    if (tid == 0) atomicAdd(&g_arrive, 1);

    // ---- merge neg bottom-3: 32 warp entries -> 1, per class ----
    const int cl = tid & (CPB - 1);
    const int g  = tid >> 4;
    float m0, m1, m2;
    if (g < 32) {
        m0 = s_w3[0*512 + g*CPB + cl];
        m1 = s_w3[1*512 + g*CPB + cl];
        m2 = s_w3[2*512 + g*CPB + cl];
    }
    for (int s = 16; s > 0; s >>= 1) {
        __syncthreads();
        if (g < s) {
            float v0 = s_w3[0*512 + (g+s)*CPB + cl];
            float v1 = s_w3[1*512 + (g+s)*CPB + cl];
            float v2 = s_w3[2*512 + (g+s)*CPB + cl];
            MERGE3(m0, m1, m2, v0, v1, v2)
            s_w3[0*512 + g*CPB + cl] = m0;
            s_w3[1*512 + g*CPB + cl] = m1;
            s_w3[2*512 + g*CPB + cl] = m2;
        }
    }
    __syncthreads();

    if (tid < CPB) {
        f_q[tid][0] = sigm_(s_w3[0*512 + tid]);
        f_q[tid][1] = sigm_(s_w3[1*512 + tid]);
        f_q[tid][2] = sigm_(s_w3[2*512 + tid]);
        f_cnt[tid]  = s_ccnt[tid];
    }
    __syncthreads();

    // ---- scan private segments: sigmoid, bottom-4 p, spos, dneg ----
    const int   cnt = f_cnt[cl];
    const int   nn  = min(3, Bn - cnt);
    const float q0 = f_q[cl][0], q1 = f_q[cl][1], q2 = f_q[cl][2];
    const float w0 = (0 < nn) ? 1.0f : 0.0f;
    const float w1 = (1 < nn) ? 1.0f : 0.0f;
    const float w2 = (2 < nn) ? 1.0f : 0.0f;

    float a0 = INFINITY, a1 = INFINITY, a2 = INFINITY, a3 = INFINITY;
    float spos = 0.0f, sdn = 0.0f;
    {
        const float* cbase = s_pbuf + cl * CSTR;
        const int*   tbase = s_tc + cl * 257;
        #pragma unroll
        for (int t4 = 0; t4 < 4; t4++) {
            const int tseg  = g * 4 + t4;
            const int bound = min(tbase[tseg], 8);
            const float* sp = cbase + tseg * SEGW;
            for (int k = 0; k < bound; k++) {
                float xr = sp[k];
                float p  = sigm_(xr);
                spos += p;
                sdn += w0 * fabsf(p - q0) + w1 * fabsf(p - q1) + w2 * fabsf(p - q2);
                float h0 = fmaxf(a0, p); a0 = fminf(a0, p);
                float h1 = fmaxf(a1, h0); a1 = fminf(a1, h0);
                float h2 = fmaxf(a2, h1); a2 = fminf(a2, h1);
                a3 = fminf(a3, h2);
            }
        }
    }
    const int base = g * CPB + cl;
    s_w4[base] = a0; s_w4[1024 + base] = a1;
    s_w4[2048 + base] = a2; s_w4[3072 + base] = a3;
    s_red[base] = sdn; s_sp[base] = spos;

    for (int s = GRP >> 1; s > 0; s >>= 1) {
        __syncthreads();
        if (g < s) {
            const int b = (g + s) * CPB + cl;
            #pragma unroll
            for (int j = 0; j < 4; j++) {
                float v = s_w4[j * 1024 + b];
                float h0 = fmaxf(a0, v); a0 = fminf(a0, v);
                float h1 = fmaxf(a1, h0); a1 = fminf(a1, h0);
                float h2 = fmaxf(a2, h1); a2 = fminf(a2, h1);
                a3 = fminf(a3, h2);
            }
            s_w4[base] = a0; s_w4[1024 + base] = a1;
            s_w4[2048 + base] = a2; s_w4[3072 + base] = a3;
            s_red[base] += s_red[b];
            s_sp[base]  += s_sp[b];
        }
    }
    __syncthreads();

    // ---- per-class finalize: analytic dpos + scaled dneg (into smem) ----
    if (tid < CPB) {
        const int c2  = tid;
        const int npc = f_cnt[c2];
        const int t4  = min(4, npc);
        const int m   = min(3, max(npc - 1, 0));
        const int nn2 = min(3, Bn - npc);
        float tv[4] = { s_w4[c2], s_w4[1024 + c2], s_w4[2048 + c2], s_w4[3072 + c2] };
        float Tm = 0.0f;
        #pragma unroll
        for (int j = 0; j < 3; j++) if (j < m) Tm += tv[j];
        float Sh = 0.0f;
        #pragma unroll
        for (int r = 0; r < 4; r++) if (r < t4) Sh += tv[r];
        float tail = (float)m * (s_sp[c2] - Sh) - (float)(npc - t4) * Tm;
        float head = 0.0f;
        #pragma unroll
        for (int r = 0; r < 4; r++) {
            if (r < t4) {
                #pragma unroll
                for (int j = 0; j < 4; j++) {
                    if (j != r) {
                        int pa2 = j - (j > r ? 1 : 0);
                        if (pa2 < m) head += fabsf(tv[r] - tv[j]);
                    }
                }
            }
        }
        s_dpl[c2] = (float)nn2 * (tail + head);
        s_dnl[c2] = (float)m * s_red[c2];
    }

    // ---- wait for all blocks' counts ----
    if (tid == 0) {
        volatile int* va = &g_arrive;
        while (*va < NB1) { }
    }
    __syncthreads();
    __threadfence();

    // ---- stage all 2000 counts into (now free) s_pbuf ----
    int* sci = (int*)s_pbuf;
    {
        const volatile int* vc = (const volatile int*)g_cnt;
        for (int i = tid; i < Cn; i += T1) sci[i] = vc[i];
    }
    __syncthreads();

    // ---- minority test for this block's 16 classes (16 warps) ----
    if (wrp < CPB) {
        const int cg = bIdx * CPB + wrp;
        const int v  = sci[cg];
        int S = 0;
        for (int c2 = lane; c2 < Cn; c2 += 32) {
            int v2 = sci[c2];
            bool le = (v2 < v) || (v2 == v && c2 <= cg);
            S += le ? v2 : 0;
        }
        #pragma unroll
        for (int o = 16; o > 0; o >>= 1) S += __shfl_xor_sync(0xffffffffu, S, o);
        if (lane == 0) s_flag[wrp] = ((S <= Bn / 2) && (v >= 2)) ? 1 : 0;
    }
    __syncthreads();

    // ---- per-block masked partials + ticket ----
    if (tid == 0) {
        float pdp = 0.0f, pdn = 0.0f;
        #pragma unroll
        for (int i = 0; i < CPB; i++) {
            if (s_flag[i]) { pdp += s_dpl[i]; pdn += s_dnl[i]; }
        }
        g_pdp[bIdx] = pdp;
        g_pdn[bIdx] = pdn;
        __threadfence();
        int tck = atomicAdd(&g_tick, 1);
        s_last = (tck == NB1 - 1) ? 1 : 0;
    }
    __syncthreads();

    // ---- last block: final combine ----
    if (s_last) {
        __threadfence();
        float dp = 0.0f, dn = 0.0f, bc = 0.0f;
        if (tid < NB1) {
            dp = ((const volatile float*)g_pdp)[tid];
            dn = ((const volatile float*)g_pdn)[tid];
            bc = ((const volatile float*)g_bceB)[tid];
        }
        #pragma unroll
        for (int o = 16; o > 0; o >>= 1) {
            dp += __shfl_xor_sync(0xffffffffu, dp, o);
            dn += __shfl_xor_sync(0xffffffffu, dn, o);
            bc += __shfl_xor_sync(0xffffffffu, bc, o);
        }
        if (lane == 0 && wrp < 4) { s_fr[0][wrp] = dp; s_fr[1][wrp] = dn; s_fr[2][wrp] = bc; }
        __syncthreads();
        if (tid == 0) {
            float fdp = s_fr[0][0] + s_fr[0][1] + s_fr[0][2] + s_fr[0][3];
            float fdn = s_fr[1][0] + s_fr[1][1] + s_fr[1][2] + s_fr[1][3];
            float fbc = s_fr[2][0] + s_fr[2][1] + s_fr[2][2] + s_fr[2][3];
            float crl = fmaxf(fdp - fdn + 1.0f, 0.0f);        // MARGIN = 1
            float bce_mean = fbc / (float)(Bn * Cn);
            out[0] = 0.001f * crl + 0.999f * bce_mean;        // ALPHA = 0.001
            g_arrive = 0;                                      // reset for graph replay
            g_tick   = 0;
        }
    }
}

extern "C" void kernel_launch(void* const* d_in, const int* in_sizes, int n_in,
                              void* d_out, int out_size)
{
    (void)in_sizes; (void)n_in; (void)out_size;
    const float* inp = (const float*)d_in[0];
    const float* tgt = (const float*)d_in[1];
    cudaFuncSetAttribute(k1, cudaFuncAttributeMaxDynamicSharedMemorySize, SM_BYTES);
    k1<<<NB1, T1, SM_BYTES>>>(inp, tgt, (float*)d_out);
}